// round 13
// baseline (speedup 1.0000x reference)
#include <cuda_runtime.h>
#include <cuda_bf16.h>
#include <cstdint>

// TensorProductScatter: R8 warp-per-edge kernel (best, 213us), but edges are
// processed in DST-SORTED order via an in-kernel counting sort. All ~16 RMW
// touches of each output line then occur in a tight window -> the line stays
// L2-resident between touches, cutting the ~420 MB of out-region DRAM RMW
// refetch that has been invariant across all prior variants.
// Weights become randomly-ordered 640B-granule reads; B300 HBM handles
// arbitrary stride at 88-92% uniformity (LTS binds first), so ~free.

#define MULC 32
#define ROWF 352            // 32 + 96 + 96 + 32 + 96
#define WARPS_PER_BLOCK 8
#define MAX_E 800000
#define MAX_N 50000

__device__ int d_counts[MAX_N];
__device__ int d_wptr[MAX_N];
__device__ int d_perm[MAX_E];

// ---------------- preprocessing: counting sort by dst ----------------

__global__ void tps_zero_counts(int N) {
    int i = blockIdx.x * blockDim.x + threadIdx.x;
    if (i < N) d_counts[i] = 0;
}

__global__ void tps_hist(const int* __restrict__ edge_dst, int E) {
    int e = blockIdx.x * blockDim.x + threadIdx.x;
    if (e < E) atomicAdd(&d_counts[edge_dst[e]], 1);
}

__global__ __launch_bounds__(1024) void tps_scan(int N) {
    __shared__ int partial[1024];
    const int t = threadIdx.x;
    const int chunk = (N + 1023) / 1024;
    const int start = t * chunk;
    const int end   = min(start + chunk, N);

    int sum = 0;
    for (int i = start; i < end; i++) sum += d_counts[i];
    partial[t] = sum;
    __syncthreads();
    for (int d = 1; d < 1024; d <<= 1) {
        int v = (t >= d) ? partial[t - d] : 0;
        __syncthreads();
        partial[t] += v;
        __syncthreads();
    }
    int run = (t == 0) ? 0 : partial[t - 1];
    for (int i = start; i < end; i++) {
        d_wptr[i] = run;
        run += d_counts[i];
    }
}

__global__ void tps_fill(const int* __restrict__ edge_dst, int E) {
    int e = blockIdx.x * blockDim.x + threadIdx.x;
    if (e < E) {
        int pos = atomicAdd(&d_wptr[edge_dst[e]], 1);
        d_perm[pos] = e;
    }
}

// ---------------- output zero ----------------

__global__ void tps_zero_kernel(float4* __restrict__ out, int n4) {
    int i = blockIdx.x * blockDim.x + threadIdx.x;
    if (i < n4) out[i] = make_float4(0.f, 0.f, 0.f, 0.f);
}

// ---------------- scatter: warp per (dst-sorted) edge ----------------

__device__ __forceinline__ uint32_t smem_u32(const void* p) {
    uint32_t a;
    asm("{ .reg .u64 t; cvta.to.shared.u64 t, %1; cvt.u32.u64 %0, t; }"
        : "=r"(a) : "l"(p));
    return a;
}

__global__ __launch_bounds__(WARPS_PER_BLOCK * 32)
void tps_scatter_kernel(const float* __restrict__ x,
                        const float* __restrict__ edge_attr,
                        const float* __restrict__ edge_weight,
                        const int*   __restrict__ edge_dst,
                        const int*   __restrict__ edge_src,
                        float*       __restrict__ out,
                        int E) {
    __shared__ __align__(16) float sm_o[WARPS_PER_BLOCK][ROWF];

    const int wb   = threadIdx.x >> 5;
    const int lane = threadIdx.x & 31;
    const long long wi = (long long)blockIdx.x * WARPS_PER_BLOCK + wb;
    if (wi >= E) return;

    // Dst-sorted edge id (warp-uniform broadcast load)
    const int e = __ldg(d_perm + wi);

    const int s = __ldg(edge_src + e);
    const int d = __ldg(edge_dst + e);
    const float4 a = __ldg(reinterpret_cast<const float4*>(edge_attr) + e);
    const float a0 = a.x, a1x = a.y, a1y = a.z, a1z = a.w;

    // x gather: L2-resident table
    const float* xrow = x + (long long)s * (4 * MULC);
    const float xs0 = __ldg(xrow + lane);
    const float x1a = __ldg(xrow + MULC + 3 * lane + 0);
    const float x1b = __ldg(xrow + MULC + 3 * lane + 1);
    const float x1c = __ldg(xrow + MULC + 3 * lane + 2);

    // Streaming weights (read-once: evict-first). Random 640B granules in
    // sorted order — HBM stride-uniform, LTS binds first.
    const float* wrow = edge_weight + (long long)e * (5 * MULC);
    const float w0 = __ldcs(wrow + 0 * MULC + lane);
    const float w1 = __ldcs(wrow + 1 * MULC + lane);
    const float w2 = __ldcs(wrow + 2 * MULC + lane);
    const float w3 = __ldcs(wrow + 3 * MULC + lane);
    const float w4 = __ldcs(wrow + 4 * MULC + lane);

    const float INV_SQRT3 = 0.5773502691896258f;
    const float INV_SQRT2 = 0.7071067811865476f;

    const float o0  = w0 * xs0 * a0;
    const float w1x = w1 * xs0;
    const float o1x = w1x * a1x, o1y = w1x * a1y, o1z = w1x * a1z;
    const float w2a = w2 * a0;
    const float o2x = w2a * x1a, o2y = w2a * x1b, o2z = w2a * x1c;
    const float dot = x1a * a1x + x1b * a1y + x1c * a1z;
    const float o3  = w3 * dot * INV_SQRT3;
    const float cx  = x1b * a1z - x1c * a1y;
    const float cy  = x1c * a1x - x1a * a1z;
    const float cz  = x1a * a1y - x1b * a1x;
    const float w4s = w4 * INV_SQRT2;
    const float o4x = w4s * cx, o4y = w4s * cy, o4z = w4s * cz;

    // Stage the 352-float row (stride-3: gcd(3,32)=1 -> conflict-free)
    float* r = sm_o[wb];
    r[lane]                = o0;
    r[MULC + 3 * lane + 0] = o1x;
    r[MULC + 3 * lane + 1] = o1y;
    r[MULC + 3 * lane + 2] = o1z;
    r[128  + 3 * lane + 0] = o2x;
    r[128  + 3 * lane + 1] = o2y;
    r[128  + 3 * lane + 2] = o2z;
    r[224  + lane]         = o3;
    r[256  + 3 * lane + 0] = o4x;
    r[256  + 3 * lane + 1] = o4y;
    r[256  + 3 * lane + 2] = o4z;
    __syncwarp();

    // TMA bulk-reduce: engine reads smem row, f32-adds into out[dst].
    if (lane == 0) {
        asm volatile("fence.proxy.async.shared::cta;" ::: "memory");
        float*   gptr  = out + (long long)d * ROWF;
        uint32_t saddr = smem_u32(r);
        asm volatile(
            "cp.reduce.async.bulk.global.shared::cta.bulk_group.add.f32 "
            "[%0], [%1], %2;"
            :: "l"(gptr), "r"(saddr), "r"((int)(ROWF * sizeof(float)))
            : "memory");
        asm volatile("cp.async.bulk.commit_group;" ::: "memory");
        asm volatile("cp.async.bulk.wait_group 0;" ::: "memory");
    }
}

// ---------------- launch ----------------

extern "C" void kernel_launch(void* const* d_in, const int* in_sizes, int n_in,
                              void* d_out, int out_size) {
    const float* x           = (const float*)d_in[0];
    const float* edge_attr   = (const float*)d_in[1];
    const float* edge_weight = (const float*)d_in[2];
    const int*   edge_dst    = (const int*)d_in[3];
    const int*   edge_src    = (const int*)d_in[4];
    float* out = (float*)d_out;

    const int E = in_sizes[3];
    const int N = out_size / ROWF;

    // Counting sort by dst
    tps_zero_counts<<<(N + 255) / 256, 256>>>(N);
    tps_hist<<<(E + 255) / 256, 256>>>(edge_dst, E);
    tps_scan<<<1, 1024>>>(N);
    tps_fill<<<(E + 255) / 256, 256>>>(edge_dst, E);

    // Zero the (poisoned) output
    int n4 = out_size / 4;
    tps_zero_kernel<<<(n4 + 255) / 256, 256>>>((float4*)out, n4);

    // Warp per dst-sorted edge
    int blocks = (E + WARPS_PER_BLOCK - 1) / WARPS_PER_BLOCK;
    tps_scatter_kernel<<<blocks, WARPS_PER_BLOCK * 32>>>(
        x, edge_attr, edge_weight, edge_dst, edge_src, out, E);
}

// round 15
// speedup vs baseline: 1.3914x; 1.3914x over previous
#include <cuda_runtime.h>
#include <cuda_bf16.h>
#include <cstdint>

// TensorProductScatter: per-edge e3nn tensor product + scatter-add.
// R8 structure (best: warp-per-edge NATURAL order, smem-staged row, TMA
// cp.reduce.async.bulk flush) + one change: the x[src] row is gathered with
// 4 COALESCED loads (1 wavefront each) and redistributed to channel order
// with 9 shuffles, replacing the 3 stride-3 scalar loads that cost 9
// wavefronts. Per-edge L1tex wavefronts: 29 -> 23 (L1 was the top SOL at 78.9%).

#define MULC 32
#define ROWF 352            // 32 + 96 + 96 + 32 + 96
#define WARPS_PER_BLOCK 8
#define FULLM 0xFFFFFFFFu

__device__ __forceinline__ uint32_t smem_u32(const void* p) {
    uint32_t a;
    asm("{ .reg .u64 t; cvta.to.shared.u64 t, %1; cvt.u32.u64 %0, t; }"
        : "=r"(a) : "l"(p));
    return a;
}

__global__ void tps_zero_kernel(float4* __restrict__ out, int n4) {
    int i = blockIdx.x * blockDim.x + threadIdx.x;
    if (i < n4) out[i] = make_float4(0.f, 0.f, 0.f, 0.f);
}

__global__ __launch_bounds__(WARPS_PER_BLOCK * 32)
void tps_scatter_kernel(const float* __restrict__ x,
                        const float* __restrict__ edge_attr,
                        const float* __restrict__ edge_weight,
                        const int*   __restrict__ edge_dst,
                        const int*   __restrict__ edge_src,
                        float*       __restrict__ out,
                        int E) {
    __shared__ __align__(16) float sm_o[WARPS_PER_BLOCK][ROWF];

    const int wb   = threadIdx.x >> 5;
    const int lane = threadIdx.x & 31;
    const long long e = (long long)blockIdx.x * WARPS_PER_BLOCK + wb;
    if (e >= E) return;

    // Uniform (warp-broadcast) loads
    const int s = __ldg(edge_src + e);
    const int d = __ldg(edge_dst + e);
    const float4 a = __ldg(reinterpret_cast<const float4*>(edge_attr) + e);
    const float a0 = a.x, a1x = a.y, a1y = a.z, a1z = a.w;

    // x row: 4 coalesced loads (1 wavefront each; L2-resident table)
    const float* xrow = x + (long long)s * (4 * MULC);
    const float xs0 = __ldg(xrow + lane);                 // xs0[lane]
    const float v0  = __ldg(xrow + MULC + 0 * 32 + lane); // x1flat[lane]
    const float v1  = __ldg(xrow + MULC + 1 * 32 + lane); // x1flat[32+lane]
    const float v2  = __ldg(xrow + MULC + 2 * 32 + lane); // x1flat[64+lane]

    // Streaming weights (read-once: evict-first)
    const float* wrow = edge_weight + e * (5 * MULC);
    const float w0 = __ldcs(wrow + 0 * MULC + lane);
    const float w1 = __ldcs(wrow + 1 * MULC + lane);
    const float w2 = __ldcs(wrow + 2 * MULC + lane);
    const float w3 = __ldcs(wrow + 3 * MULC + lane);
    const float w4 = __ldcs(wrow + 4 * MULC + lane);

    // Redistribute x1flat -> channel order: lane u needs x1flat[3u+k], k=0..2
    float x1v[3];
    #pragma unroll
    for (int k = 0; k < 3; k++) {
        const int m    = 3 * lane + k;    // 0..95
        const int src  = m & 31;
        const int slot = m >> 5;          // which of v0/v1/v2
        const float t0 = __shfl_sync(FULLM, v0, src);
        const float t1 = __shfl_sync(FULLM, v1, src);
        const float t2 = __shfl_sync(FULLM, v2, src);
        x1v[k] = (slot == 0) ? t0 : ((slot == 1) ? t1 : t2);
    }
    const float x1a = x1v[0], x1b = x1v[1], x1c = x1v[2];

    const float INV_SQRT3 = 0.5773502691896258f;
    const float INV_SQRT2 = 0.7071067811865476f;

    const float o0  = w0 * xs0 * a0;
    const float w1x = w1 * xs0;
    const float o1x = w1x * a1x, o1y = w1x * a1y, o1z = w1x * a1z;
    const float w2a = w2 * a0;
    const float o2x = w2a * x1a, o2y = w2a * x1b, o2z = w2a * x1c;
    const float dot = x1a * a1x + x1b * a1y + x1c * a1z;
    const float o3  = w3 * dot * INV_SQRT3;
    const float cx  = x1b * a1z - x1c * a1y;
    const float cy  = x1c * a1x - x1a * a1z;
    const float cz  = x1a * a1y - x1b * a1x;
    const float w4s = w4 * INV_SQRT2;
    const float o4x = w4s * cx, o4y = w4s * cy, o4z = w4s * cz;

    // Stage the 352-float row (stride-3: gcd(3,32)=1 -> conflict-free)
    float* r = sm_o[wb];
    r[lane]                = o0;
    r[MULC + 3 * lane + 0] = o1x;
    r[MULC + 3 * lane + 1] = o1y;
    r[MULC + 3 * lane + 2] = o1z;
    r[128  + 3 * lane + 0] = o2x;
    r[128  + 3 * lane + 1] = o2y;
    r[128  + 3 * lane + 2] = o2z;
    r[224  + lane]         = o3;
    r[256  + 3 * lane + 0] = o4x;
    r[256  + 3 * lane + 1] = o4y;
    r[256  + 3 * lane + 2] = o4z;
    __syncwarp();

    // TMA bulk-reduce: engine reads smem row, f32-adds into out[dst].
    if (lane == 0) {
        asm volatile("fence.proxy.async.shared::cta;" ::: "memory");
        float*   gptr  = out + (long long)d * ROWF;
        uint32_t saddr = smem_u32(r);
        asm volatile(
            "cp.reduce.async.bulk.global.shared::cta.bulk_group.add.f32 "
            "[%0], [%1], %2;"
            :: "l"(gptr), "r"(saddr), "r"((int)(ROWF * sizeof(float)))
            : "memory");
        asm volatile("cp.async.bulk.commit_group;" ::: "memory");
        asm volatile("cp.async.bulk.wait_group 0;" ::: "memory");
    }
}

extern "C" void kernel_launch(void* const* d_in, const int* in_sizes, int n_in,
                              void* d_out, int out_size) {
    const float* x           = (const float*)d_in[0];
    const float* edge_attr   = (const float*)d_in[1];
    const float* edge_weight = (const float*)d_in[2];
    const int*   edge_dst    = (const int*)d_in[3];
    const int*   edge_src    = (const int*)d_in[4];
    float* out = (float*)d_out;

    const int E = in_sizes[3];

    int n4 = out_size / 4;
    tps_zero_kernel<<<(n4 + 255) / 256, 256>>>((float4*)out, n4);

    int blocks = (E + WARPS_PER_BLOCK - 1) / WARPS_PER_BLOCK;
    tps_scatter_kernel<<<blocks, WARPS_PER_BLOCK * 32>>>(
        x, edge_attr, edge_weight, edge_dst, edge_src, out, E);
}